// round 14
// baseline (speedup 1.0000x reference)
#include <cuda_runtime.h>
#include <math_constants.h>

// Prefix-max (cumulative max) along H for x of shape (B=32, C=1, H=1024, W=1024), fp32.
// Layout: x[(b*H + h)*W + w]. 32768 columns (b,w), scan length H=1024.
//
// NEW: H split across 4 CTA segments with a chained inter-CTA carry
// (decoupled scan). Grid = 8192 = 4 segments x 2048 column-tiles,
// bid = s*2048 + t: segment s's predecessor (s-1, same t) is 2048 bids
// earlier (>= 2 full waves at 888 resident CTAs), so the spin-wait is
// effectively never taken. Each flag has exactly ONE reader, which resets
// it after consuming -> arrays self-clean across CUDA-graph replays
// (device globals start zero-initialized). fmaxf is associative/exact ->
// result is deterministic regardless of timing.
//
// Per CTA: 256 threads, 16 cols x 256 rows (16 chunks x 16 rows/thread),
// 64B warp segments (proven best), warp-shuffle chunk scan, 2 barriers.

#define H_DIM 1024
#define W_DIM 1024
#define SEGS 4
#define TILES 2048
#define COLS_PER_BLOCK 16
#define CHUNKS 16
#define ROWS_PER_THREAD 16
#define SEG_ROWS 256          // CHUNKS * ROWS_PER_THREAD

__device__ float g_agg[(SEGS - 1) * TILES * COLS_PER_BLOCK];   // 384 KB
__device__ int   g_flag[(SEGS - 1) * TILES];                   // zero-init; self-cleaning

__global__ __launch_bounds__(256, 6)
void cummax_kernel(const float* __restrict__ x, float* __restrict__ out) {
    const int tid   = threadIdx.x;
    const int c     = tid & (COLS_PER_BLOCK - 1);   // 0..15
    const int chunk = tid >> 4;                     // 0..15
    const int wid   = tid >> 5;                     // 0..7
    const int lane  = tid & 31;

    const int bid = blockIdx.x;
    const int s   = bid >> 11;          // segment 0..3
    const int t   = bid & (TILES - 1);  // column-tile 0..2047

    const int col = t * COLS_PER_BLOCK + c;   // 1024 % 16 == 0: no b straddle
    const int b   = col >> 10;
    const int w   = col & (W_DIM - 1);

    const int base = b * (H_DIM * W_DIM) + w
                   + (s * SEG_ROWS + chunk * ROWS_PER_THREAD) * W_DIM;
    const float* __restrict__ src = x   + base;
    float*       __restrict__ dst = out + base;

    // Phase 1: load 16 rows (64B warp segments), local prefix-max.
    float v[ROWS_PER_THREAD];
#pragma unroll
    for (int i = 0; i < ROWS_PER_THREAD; i++) {
        v[i] = src[i * W_DIM];
    }
#pragma unroll
    for (int i = 1; i < ROWS_PER_THREAD; i++) {
        v[i] = fmaxf(v[i], v[i - 1]);
    }

    // Phase 2: intra-CTA scan of 16 chunk totals (warp scans 2 cols, width-16).
    __shared__ float sm[CHUNKS][COLS_PER_BLOCK + 1];
    sm[chunk][c] = v[ROWS_PER_THREAD - 1];
    __syncthreads();
    {
        const int scan_col = 2 * wid + (lane >> 4);
        const int scan_ch  = lane & 15;
        float tt = sm[scan_ch][scan_col];
#pragma unroll
        for (int d = 1; d < 16; d <<= 1) {
            float o = __shfl_up_sync(0xFFFFFFFFu, tt, d, 16);
            if (scan_ch >= d) tt = fmaxf(tt, o);
        }
        sm[scan_ch][scan_col] = tt;
    }
    __syncthreads();

    const float total = sm[CHUNKS - 1][c];   // CTA-inclusive total, column c

    // Phase 3: inter-CTA carry from segment s-1 (chained).
    float carry = -CUDART_INF_F;
    if (s > 0) {
        const int prev = (s - 1) * TILES + t;
        if (tid == 0) {
            volatile int* f = &g_flag[prev];
            while (*f == 0) { __nanosleep(64); }
            __threadfence();
        }
        __syncthreads();
        carry = __ldcg(&g_agg[prev * COLS_PER_BLOCK + c]);
        __syncthreads();
        if (tid == 0) {
            *((volatile int*)&g_flag[prev]) = 0;   // unique reader resets
        }
    }

    const float incl = fmaxf(carry, total);   // segment-inclusive prefix, column c

    // Phase 4: publish (before stores, to unblock successor ASAP).
    if (s < SEGS - 1) {
        if (tid < COLS_PER_BLOCK) {
            g_agg[(s * TILES + t) * COLS_PER_BLOCK + tid] = incl;
        }
        __threadfence();
        __syncthreads();
        if (tid == 0) {
            atomicExch(&g_flag[s * TILES + t], 1);
        }
    }

    // Phase 5: apply carry and store.
    const float excl = (chunk > 0) ? sm[chunk - 1][c] : -CUDART_INF_F;
    const float m = fmaxf(carry, excl);
#pragma unroll
    for (int i = 0; i < ROWS_PER_THREAD; i++) {
        dst[i * W_DIM] = fmaxf(v[i], m);
    }
}

extern "C" void kernel_launch(void* const* d_in, const int* in_sizes, int n_in,
                              void* d_out, int out_size) {
    const float* x = (const float*)d_in[0];
    float* out = (float*)d_out;

    cummax_kernel<<<SEGS * TILES, 256>>>(x, out);   // grid 8192
}

// round 15
// speedup vs baseline: 1.1467x; 1.1467x over previous
#include <cuda_runtime.h>
#include <math_constants.h>

// Prefix-max (cumulative max) along H for x of shape (B=32, C=1, H=1024, W=1024), fp32.
// Layout: x[(b*H + h)*W + w]. 32768 independent columns (b,w), scan length H=1024.
//
// FINAL (best scored across 14 rounds: 45.088us, reproduced 45.184us).
// 512-thread block owns 16 consecutive float-columns x full H, processed as
// TWO halves of 512 rows (16 rows/thread, v[16] -> 40 regs -> 3 CTAs/SM via
// __launch_bounds__(512,3)). Grid 2048.
// Measured findings that fix this design:
//   - 64B warp segments beat 32B (L2 pressure) and tie 128B lines on DRAM.
//   - ~70-72% DRAM is the ceiling for this 256MB mixed read+write stream:
//     insensitive to occupancy (47-92%), vector width, cache hints
//     (__ldcs/__stcs regressed), single-wave grids, and decoupled
//     multi-CTA scans (both regressed the scored time).
//   - Warp-shuffle chunk scan keeps it at 2 barriers per half.
//   thread t: c = t & 15, chunk = t >> 4 (32 chunks of 16 rows per half).
//   Per half: coalesced loads, local prefix-max, chunk totals -> smem
//   (1 barrier), warp-per-column shuffle scan (5 rounds, no barrier),
//   read-back (1 barrier), apply carry (incl. cross-half), coalesced stores.

#define H_DIM 1024
#define W_DIM 1024
#define COLS_PER_BLOCK 16
#define CHUNKS 32
#define ROWS_PER_THREAD 16   // per half
#define HALF_ROWS 512        // CHUNKS * ROWS_PER_THREAD

__global__ __launch_bounds__(512, 3)
void cummax_kernel(const float* __restrict__ x, float* __restrict__ out) {
    const int tid   = threadIdx.x;
    const int c     = tid & (COLS_PER_BLOCK - 1);   // 0..15
    const int chunk = tid >> 4;                     // 0..31
    const int wid   = tid >> 5;                     // 0..15
    const int lane  = tid & 31;

    const int col = blockIdx.x * COLS_PER_BLOCK + c;  // 1024 % 16 == 0: no b straddle
    const int b   = col >> 10;
    const int w   = col & (W_DIM - 1);

    const int base0 = b * (H_DIM * W_DIM) + w + chunk * ROWS_PER_THREAD * W_DIM;

    __shared__ float s[2][CHUNKS][COLS_PER_BLOCK + 1];   // double buffer, padded

    float carry = -CUDART_INF_F;

#pragma unroll
    for (int half = 0; half < 2; half++) {
        const int base = base0 + half * HALF_ROWS * W_DIM;
        const float* __restrict__ src = x   + base;
        float*       __restrict__ dst = out + base;

        // Load 16 rows (coalesced: warp covers 2 rows x 64B fully-used segments).
        float v[ROWS_PER_THREAD];
#pragma unroll
        for (int i = 0; i < ROWS_PER_THREAD; i++) {
            v[i] = src[i * W_DIM];
        }
#pragma unroll
        for (int i = 1; i < ROWS_PER_THREAD; i++) {
            v[i] = fmaxf(v[i], v[i - 1]);
        }

        // Cross-chunk inclusive max-scan of totals via warp shuffles.
        s[half][chunk][c] = v[ROWS_PER_THREAD - 1];
        __syncthreads();

        // Warp `wid` scans column `wid`: lane = chunk index. 16 warps, 16 columns.
        {
            float t = s[half][lane][wid];
#pragma unroll
            for (int d = 1; d < 32; d <<= 1) {
                float o = __shfl_up_sync(0xFFFFFFFFu, t, d);
                if (lane >= d) t = fmaxf(t, o);
            }
            s[half][lane][wid] = t;
        }
        __syncthreads();

        // Exclusive carry (preceding chunks of this half + previous halves).
        const float excl = (chunk > 0) ? s[half][chunk - 1][c] : -CUDART_INF_F;
        const float m = fmaxf(carry, excl);

#pragma unroll
        for (int i = 0; i < ROWS_PER_THREAD; i++) {
            dst[i * W_DIM] = fmaxf(v[i], m);
        }

        carry = fmaxf(carry, s[half][CHUNKS - 1][c]);
    }
}

extern "C" void kernel_launch(void* const* d_in, const int* in_sizes, int n_in,
                              void* d_out, int out_size) {
    const float* x = (const float*)d_in[0];
    float* out = (float*)d_out;

    const int total_cols = 32 * W_DIM;                        // 32768
    const int grid = total_cols / COLS_PER_BLOCK;             // 2048
    cummax_kernel<<<grid, 512>>>(x, out);
}

// round 16
// speedup vs baseline: 1.1475x; 1.0007x over previous
#include <cuda_runtime.h>
#include <math_constants.h>

// Prefix-max (cumulative max) along H for x of shape (B=32, C=1, H=1024, W=1024), fp32.
// Layout: x[(b*H + h)*W + w]. 32768 independent columns (b,w), scan length H=1024.
//
// Geometry = banked best (R5, 45.088us): 512-thread block owns 16 consecutive
// float-columns x full H, TWO halves of 512 rows (16 rows/thread, v[16],
// 40 regs, 3 CTAs/SM). Grid 2048. 64B warp segments.
// SINGLE-VARIABLE CHANGE vs banked best: stores use __stwt (write-through).
// Rationale: 128MB of writes vs 126MB L2 means the default write-back policy
// emits bursty eviction-time writebacks that interleave poorly with demand
// reads; write-through gives the DRAM controller a steady early write stream
// and read misses never wait on dirty-victim writebacks. Loads keep default
// caching (R10 showed changing the LOAD policy regresses).

#define H_DIM 1024
#define W_DIM 1024
#define COLS_PER_BLOCK 16
#define CHUNKS 32
#define ROWS_PER_THREAD 16   // per half
#define HALF_ROWS 512        // CHUNKS * ROWS_PER_THREAD

__global__ __launch_bounds__(512, 3)
void cummax_kernel(const float* __restrict__ x, float* __restrict__ out) {
    const int tid   = threadIdx.x;
    const int c     = tid & (COLS_PER_BLOCK - 1);   // 0..15
    const int chunk = tid >> 4;                     // 0..31
    const int wid   = tid >> 5;                     // 0..15
    const int lane  = tid & 31;

    const int col = blockIdx.x * COLS_PER_BLOCK + c;  // 1024 % 16 == 0: no b straddle
    const int b   = col >> 10;
    const int w   = col & (W_DIM - 1);

    const int base0 = b * (H_DIM * W_DIM) + w + chunk * ROWS_PER_THREAD * W_DIM;

    __shared__ float s[2][CHUNKS][COLS_PER_BLOCK + 1];   // double buffer, padded

    float carry = -CUDART_INF_F;

#pragma unroll
    for (int half = 0; half < 2; half++) {
        const int base = base0 + half * HALF_ROWS * W_DIM;
        const float* __restrict__ src = x   + base;
        float*       __restrict__ dst = out + base;

        // Load 16 rows (coalesced: warp covers 2 rows x 64B fully-used segments).
        float v[ROWS_PER_THREAD];
#pragma unroll
        for (int i = 0; i < ROWS_PER_THREAD; i++) {
            v[i] = src[i * W_DIM];
        }
#pragma unroll
        for (int i = 1; i < ROWS_PER_THREAD; i++) {
            v[i] = fmaxf(v[i], v[i - 1]);
        }

        // Cross-chunk inclusive max-scan of totals via warp shuffles.
        s[half][chunk][c] = v[ROWS_PER_THREAD - 1];
        __syncthreads();

        // Warp `wid` scans column `wid`: lane = chunk index. 16 warps, 16 columns.
        {
            float t = s[half][lane][wid];
#pragma unroll
            for (int d = 1; d < 32; d <<= 1) {
                float o = __shfl_up_sync(0xFFFFFFFFu, t, d);
                if (lane >= d) t = fmaxf(t, o);
            }
            s[half][lane][wid] = t;
        }
        __syncthreads();

        // Exclusive carry (preceding chunks of this half + previous halves).
        const float excl = (chunk > 0) ? s[half][chunk - 1][c] : -CUDART_INF_F;
        const float m = fmaxf(carry, excl);

        // Store: write-through (steady write stream, no eviction bursts).
#pragma unroll
        for (int i = 0; i < ROWS_PER_THREAD; i++) {
            __stwt(dst + i * W_DIM, fmaxf(v[i], m));
        }

        carry = fmaxf(carry, s[half][CHUNKS - 1][c]);
    }
}

extern "C" void kernel_launch(void* const* d_in, const int* in_sizes, int n_in,
                              void* d_out, int out_size) {
    const float* x = (const float*)d_in[0];
    float* out = (float*)d_out;

    const int total_cols = 32 * W_DIM;                        // 32768
    const int grid = total_cols / COLS_PER_BLOCK;             // 2048
    cummax_kernel<<<grid, 512>>>(x, out);
}